// round 1
// baseline (speedup 1.0000x reference)
#include <cuda_runtime.h>
#include <cuda_bf16.h>

// Problem constants
#define BB 64
#define TT 1024
#define DD 64
#define HH 4
#define SPLIT 4
#define RPC 256        // key rows per CTA in kernel A
#define STRIDE 68      // smem row stride in floats (68%32==4 -> LDS.128 conflict-free)
#define NEGF (-4294967296.0f)   // float32(-2^32+1)

// Dynamic smem layout (floats)
#define OFF_KS   0
#define OFF_P4   17408            // 256*68
#define OFF_ACC  18432            // +1024
#define OFF_U    19456            // +1024
#define OFF_Q0   19712            // +256
#define OFF_QH   19776            // +64
#define OFF_WRED 19840            // +64
#define OFF_MH   19872            // +32
#define SMEM_FLOATS 19876
#define SMEM_BYTES (SMEM_FLOATS * 4)

// Cross-kernel scratch (no cudaMalloc allowed)
__device__ float4 g_pacc[BB * SPLIT * DD];   // [b][split][d] -> 4 heads packed
__device__ float  g_pm[BB * SPLIT * HH];     // running max per (b,split,h)
__device__ float  g_pl[BB * SPLIT * HH];     // exp-sum per (b,split,h)

__global__ __launch_bounds__(256) void attn_partial_kernel(
    const float* __restrict__ queries, const float* __restrict__ keys,
    const int* __restrict__ key_mask,
    const float* __restrict__ W_Q, const float* __restrict__ W_K)
{
    extern __shared__ float sm[];
    float*  ks   = sm + OFF_KS;
    float4* p4   = (float4*)(sm + OFF_P4);
    float4* accm = (float4*)(sm + OFF_ACC);
    float*  u    = sm + OFF_U;
    float*  q0   = sm + OFF_Q0;
    float*  Qh   = sm + OFF_QH;
    float*  wred = sm + OFF_WRED;
    float*  mh   = sm + OFF_MH;

    const int split = blockIdx.x;
    const int b     = blockIdx.y;
    const int t     = threadIdx.x;
    const int k0    = split * RPC;
    const int lane  = t & 31;
    const int wid   = t >> 5;

    // ---- load key tile [RPC x 64] into smem (coalesced float4) ----
    const float4* kg = (const float4*)(keys + ((size_t)b * TT + k0) * DD);
    #pragma unroll
    for (int i = 0; i < 16; i++) {
        int idx = t + i * 256;
        int row = idx >> 4, c = idx & 15;
        float4 v = kg[idx];
        *(float4*)&ks[row * STRIDE + c * 4] = v;
    }
    const int kmv = key_mask[b * TT + k0 + t];

    if (t < 64) q0[t] = queries[(size_t)b * TT * DD + t];
    __syncthreads();

    // ---- Qh[j] = sum_i q0[i] * W_Q[i][j]   (parallel over (j, i-quarter)) ----
    {
        int j = t & 63, q = t >> 6;
        float a = 0.f;
        #pragma unroll
        for (int i = q * 16; i < q * 16 + 16; i++) a += q0[i] * W_Q[i * 64 + j];
        ((float*)accm)[t] = a;
    }
    __syncthreads();
    if (t < 64) {
        float* pr = (float*)accm;
        Qh[t] = pr[t] + pr[64 + t] + pr[128 + t] + pr[192 + t];
    }
    __syncthreads();

    // ---- u[h][d] = 0.25 * sum_j W_K[d][h*16+j] * Qh[h*16+j], stored u[d*4+h] ----
    {
        int d = t & 63, h = t >> 6;
        const float4* wr  = (const float4*)(W_K + d * 64 + h * 16);
        const float4* qh4 = (const float4*)(Qh + h * 16);
        float a = 0.f;
        #pragma unroll
        for (int c = 0; c < 4; c++) {
            float4 w = wr[c]; float4 q = qh4[c];
            a += w.x * q.x + w.y * q.y + w.z * q.z + w.w * q.w;
        }
        u[d * 4 + h] = a * 0.25f;
    }
    __syncthreads();

    // ---- phase 1: thread t = key row t; scores for 4 heads ----
    float s0, s1, s2, s3;
    {
        const float4* krow = (const float4*)&ks[t * STRIDE];
        const float4* u4 = (const float4*)u;
        float a0 = 0.f, a1 = 0.f, a2 = 0.f, a3 = 0.f;
        #pragma unroll
        for (int c = 0; c < 16; c++) {
            float4 kv = krow[c];
            float4 ux = u4[4 * c + 0], uy = u4[4 * c + 1];
            float4 uz = u4[4 * c + 2], uw = u4[4 * c + 3];
            a0 += kv.x * ux.x + kv.y * uy.x + kv.z * uz.x + kv.w * uw.x;
            a1 += kv.x * ux.y + kv.y * uy.y + kv.z * uz.y + kv.w * uw.y;
            a2 += kv.x * ux.z + kv.y * uy.z + kv.z * uz.z + kv.w * uw.z;
            a3 += kv.x * ux.w + kv.y * uy.w + kv.z * uz.w + kv.w * uw.w;
        }
        // key padding mask + diagonal blinding (query position is 0 -> mask k==0)
        bool masked = (kmv != 1) || ((k0 + t) == 0);
        s0 = masked ? NEGF : a0;
        s1 = masked ? NEGF : a1;
        s2 = masked ? NEGF : a2;
        s3 = masked ? NEGF : a3;
    }

    // ---- warp+block max per head ----
    float m0 = s0, m1 = s1, m2 = s2, m3 = s3;
    #pragma unroll
    for (int o = 16; o; o >>= 1) {
        m0 = fmaxf(m0, __shfl_xor_sync(0xffffffffu, m0, o));
        m1 = fmaxf(m1, __shfl_xor_sync(0xffffffffu, m1, o));
        m2 = fmaxf(m2, __shfl_xor_sync(0xffffffffu, m2, o));
        m3 = fmaxf(m3, __shfl_xor_sync(0xffffffffu, m3, o));
    }
    if (lane == 0) {
        wred[wid * 4 + 0] = m0; wred[wid * 4 + 1] = m1;
        wred[wid * 4 + 2] = m2; wred[wid * 4 + 3] = m3;
    }
    __syncthreads();
    if (t < 4) {
        float m = wred[t];
        #pragma unroll
        for (int w = 1; w < 8; w++) m = fmaxf(m, wred[w * 4 + t]);
        mh[t] = m;
    }
    __syncthreads();

    // ---- p = exp(s - m), store packed; block sum per head ----
    float p0 = __expf(s0 - mh[0]);
    float p1 = __expf(s1 - mh[1]);
    float p2 = __expf(s2 - mh[2]);
    float p3 = __expf(s3 - mh[3]);
    p4[t] = make_float4(p0, p1, p2, p3);
    float l0 = p0, l1 = p1, l2 = p2, l3 = p3;
    #pragma unroll
    for (int o = 16; o; o >>= 1) {
        l0 += __shfl_xor_sync(0xffffffffu, l0, o);
        l1 += __shfl_xor_sync(0xffffffffu, l1, o);
        l2 += __shfl_xor_sync(0xffffffffu, l2, o);
        l3 += __shfl_xor_sync(0xffffffffu, l3, o);
    }
    if (lane == 0) {
        wred[wid * 4 + 0] = l0; wred[wid * 4 + 1] = l1;
        wred[wid * 4 + 2] = l2; wred[wid * 4 + 3] = l3;
    }
    __syncthreads();
    if (t < 4) {
        float l = wred[t];
        #pragma unroll
        for (int w = 1; w < 8; w++) l += wred[w * 4 + t];
        g_pm[(b * SPLIT + split) * HH + t] = mh[t];
        g_pl[(b * SPLIT + split) * HH + t] = l;
    }

    // ---- phase 2: weighted key sum. thread = (d, k-quarter); acc over 4 heads ----
    {
        int d = t & 63, q = t >> 6;
        float ax = 0.f, ay = 0.f, az = 0.f, aw = 0.f;
        const int kb = q * 64;
        #pragma unroll 4
        for (int kk = 0; kk < 64; kk++) {
            float kv = ks[(kb + kk) * STRIDE + d];
            float4 p = p4[kb + kk];
            ax += p.x * kv; ay += p.y * kv; az += p.z * kv; aw += p.w * kv;
        }
        accm[t] = make_float4(ax, ay, az, aw);
    }
    __syncthreads();
    if (t < 64) {
        float4 a = accm[t], c = accm[64 + t], d4 = accm[128 + t], e = accm[192 + t];
        float4 r;
        r.x = a.x + c.x + d4.x + e.x;
        r.y = a.y + c.y + d4.y + e.y;
        r.z = a.z + c.z + d4.z + e.z;
        r.w = a.w + c.w + d4.w + e.w;
        g_pacc[(b * SPLIT + split) * DD + t] = r;
    }
}

__global__ __launch_bounds__(256) void combine_ffn_kernel(
    const float* __restrict__ queries, const int* __restrict__ query_mask,
    const float* __restrict__ W_V,
    const float* __restrict__ fw1, const float* __restrict__ fw2,
    const float* __restrict__ fb1, const float* __restrict__ fb2,
    float* __restrict__ out)
{
    const int b = blockIdx.x;
    const int t = threadIdx.x;

    __shared__ float m_sm[SPLIT * HH], l_sm[SPLIT * HH], f_sm[SPLIT * HH];
    __shared__ float scale_sm[HH];
    __shared__ float s_sm[HH * DD];
    __shared__ float res_sm[DD];
    __shared__ float hid_sm[4 * DD];
    __shared__ float part_sm[256];

    if (t < SPLIT * HH) {
        m_sm[t] = g_pm[b * SPLIT * HH + t];
        l_sm[t] = g_pl[b * SPLIT * HH + t];
    }
    __syncthreads();
    if (t < HH) {
        float M = m_sm[t];
        #pragma unroll
        for (int s = 1; s < SPLIT; s++) M = fmaxf(M, m_sm[s * HH + t]);
        float L = 0.f;
        #pragma unroll
        for (int s = 0; s < SPLIT; s++) {
            float f = __expf(m_sm[s * HH + t] - M);
            f_sm[s * HH + t] = f;
            L += l_sm[s * HH + t] * f;
        }
        float qm = (float)query_mask[b * TT];   // query position 0 mask
        scale_sm[t] = qm / L;
    }
    __syncthreads();

    // s[h][d] = (sum over splits of acc * factor) * qm / L
    {
        int d = t & 63, h = t >> 6;
        const float* pa = (const float*)g_pacc;
        float S = 0.f;
        #pragma unroll
        for (int s = 0; s < SPLIT; s++)
            S += pa[((b * SPLIT + s) * DD + d) * 4 + h] * f_sm[s * HH + h];
        s_sm[h * DD + d] = S * scale_sm[h];
    }
    __syncthreads();

    // out[j] = sum_d s[h(j)][d] * W_V[d][j]; residual with queries[b,0,:]
    {
        int j = t & 63, q = t >> 6;
        int h = j >> 4;
        float a = 0.f;
        #pragma unroll
        for (int d = q * 16; d < q * 16 + 16; d++) a += s_sm[h * DD + d] * W_V[d * 64 + j];
        part_sm[t] = a;
    }
    __syncthreads();
    if (t < 64) {
        float o = part_sm[t] + part_sm[64 + t] + part_sm[128 + t] + part_sm[192 + t];
        res_sm[t] = o + queries[(size_t)b * TT * DD + t];
    }
    __syncthreads();

    // hidden = leaky_relu(res @ fw1 + fb1), 256 units
    {
        float a = fb1[t];
        #pragma unroll 8
        for (int j = 0; j < 64; j++) a += res_sm[j] * fw1[j * 256 + t];
        hid_sm[t] = (a > 0.f) ? a : 0.2f * a;
    }
    __syncthreads();

    // final = res + hidden @ fw2 + fb2
    {
        int j = t & 63, q = t >> 6;
        float a = 0.f;
        #pragma unroll 8
        for (int m = q * 64; m < q * 64 + 64; m++) a += hid_sm[m] * fw2[m * 64 + j];
        part_sm[t] = a;
    }
    __syncthreads();
    if (t < 64) {
        out[b * 64 + t] = res_sm[t] + fb2[t]
                        + part_sm[t] + part_sm[64 + t] + part_sm[128 + t] + part_sm[192 + t];
    }
}

extern "C" void kernel_launch(void* const* d_in, const int* in_sizes, int n_in,
                              void* d_out, int out_size)
{
    const float* queries = (const float*)d_in[0];
    const float* keys    = (const float*)d_in[1];
    const int*   qmask   = (const int*)d_in[2];
    const int*   kmask   = (const int*)d_in[3];
    const float* W_Q     = (const float*)d_in[4];
    const float* W_K     = (const float*)d_in[5];
    const float* W_V     = (const float*)d_in[6];
    const float* fw1     = (const float*)d_in[7];
    const float* fw2     = (const float*)d_in[8];
    const float* fb1     = (const float*)d_in[9];
    const float* fb2     = (const float*)d_in[10];
    float* out = (float*)d_out;

    cudaFuncSetAttribute(attn_partial_kernel,
                         cudaFuncAttributeMaxDynamicSharedMemorySize, SMEM_BYTES);

    attn_partial_kernel<<<dim3(SPLIT, BB), 256, SMEM_BYTES>>>(queries, keys, kmask, W_Q, W_K);
    combine_ffn_kernel<<<BB, 256>>>(queries, qmask, W_V, fw1, fw2, fb1, fb2, out);
}

// round 2
// speedup vs baseline: 1.0947x; 1.0947x over previous
#include <cuda_runtime.h>
#include <cuda_bf16.h>

// Problem constants
#define BB 64
#define TT 1024
#define DD 64
#define HH 4
#define SPLIT 4
#define RPC 256        // key rows per CTA in kernel A
#define STRIDE 68      // smem row stride in floats (68%32==4 -> LDS.128 conflict-free)
#define NEGF (-4294967296.0f)   // float32(-2^32+1)

// ---------------- kernel A smem layout (floats) ----------------
#define OFF_KS   0
#define OFF_P4   17408            // 256*68
#define OFF_ACC  18432            // +1024
#define OFF_U    19456            // +1024
#define OFF_Q0   19712            // +256
#define OFF_QH   19776            // +64
#define OFF_WRED 19840            // +64
#define OFF_MH   19872            // +32
#define SMEM_FLOATS 19876
#define SMEM_BYTES (SMEM_FLOATS * 4)

// ---------------- kernel B smem layout (floats) ----------------
#define BF_FW1   0                // 16384
#define BF_FW2   16384            // 16384
#define BF_WV    32768            // 4096
#define BF_PACC  36864            // 1024 (256 float4)
#define BF_FB1   37888            // 256
#define BF_HID   38144            // 256
#define BF_PART  38400            // 256
#define BF_SSM   38656            // 256
#define BF_QS    38912            // 64
#define BF_FB2   38976            // 64
#define BF_RES   39040            // 64
#define BF_MS    39104            // 16
#define BF_LS    39120            // 16
#define BF_FS    39136            // 16
#define BF_SC    39152            // 4
#define BSM_FLOATS 39160
#define BSM_BYTES (BSM_FLOATS * 4)

// Cross-kernel scratch (no cudaMalloc allowed)
__device__ float4 g_pacc[BB * SPLIT * DD];   // [b][split][d] -> 4 heads packed
__device__ float  g_pm[BB * SPLIT * HH];     // running max per (b,split,h)
__device__ float  g_pl[BB * SPLIT * HH];     // exp-sum per (b,split,h)

__global__ __launch_bounds__(256) void attn_partial_kernel(
    const float* __restrict__ queries, const float* __restrict__ keys,
    const int* __restrict__ key_mask,
    const float* __restrict__ W_Q, const float* __restrict__ W_K)
{
    extern __shared__ float sm[];
    float*  ks   = sm + OFF_KS;
    float4* p4   = (float4*)(sm + OFF_P4);
    float4* accm = (float4*)(sm + OFF_ACC);
    float*  u    = sm + OFF_U;
    float*  q0   = sm + OFF_Q0;
    float*  Qh   = sm + OFF_QH;
    float*  wred = sm + OFF_WRED;
    float*  mh   = sm + OFF_MH;

    const int split = blockIdx.x;
    const int b     = blockIdx.y;
    const int t     = threadIdx.x;
    const int k0    = split * RPC;
    const int lane  = t & 31;
    const int wid   = t >> 5;

    // ---- load key tile [RPC x 64] into smem (coalesced float4) ----
    const float4* kg = (const float4*)(keys + ((size_t)b * TT + k0) * DD);
    #pragma unroll
    for (int i = 0; i < 16; i++) {
        int idx = t + i * 256;
        int row = idx >> 4, c = idx & 15;
        float4 v = kg[idx];
        *(float4*)&ks[row * STRIDE + c * 4] = v;
    }
    const int kmv = key_mask[b * TT + k0 + t];

    if (t < 64) q0[t] = queries[(size_t)b * TT * DD + t];
    __syncthreads();

    // ---- Qh[j] = sum_i q0[i] * W_Q[i][j]   (parallel over (j, i-quarter)) ----
    {
        int j = t & 63, q = t >> 6;
        float a = 0.f;
        #pragma unroll
        for (int i = q * 16; i < q * 16 + 16; i++) a += q0[i] * W_Q[i * 64 + j];
        ((float*)accm)[t] = a;
    }
    __syncthreads();
    if (t < 64) {
        float* pr = (float*)accm;
        Qh[t] = pr[t] + pr[64 + t] + pr[128 + t] + pr[192 + t];
    }
    __syncthreads();

    // ---- u[h][d] = 0.25 * sum_j W_K[d][h*16+j] * Qh[h*16+j], stored u[d*4+h] ----
    {
        int d = t & 63, h = t >> 6;
        const float4* wr  = (const float4*)(W_K + d * 64 + h * 16);
        const float4* qh4 = (const float4*)(Qh + h * 16);
        float a = 0.f;
        #pragma unroll
        for (int c = 0; c < 4; c++) {
            float4 w = wr[c]; float4 q = qh4[c];
            a += w.x * q.x + w.y * q.y + w.z * q.z + w.w * q.w;
        }
        u[d * 4 + h] = a * 0.25f;
    }
    __syncthreads();

    // ---- phase 1: thread t = key row t; scores for 4 heads ----
    float s0, s1, s2, s3;
    {
        const float4* krow = (const float4*)&ks[t * STRIDE];
        const float4* u4 = (const float4*)u;
        float a0 = 0.f, a1 = 0.f, a2 = 0.f, a3 = 0.f;
        #pragma unroll
        for (int c = 0; c < 16; c++) {
            float4 kv = krow[c];
            float4 ux = u4[4 * c + 0], uy = u4[4 * c + 1];
            float4 uz = u4[4 * c + 2], uw = u4[4 * c + 3];
            a0 += kv.x * ux.x + kv.y * uy.x + kv.z * uz.x + kv.w * uw.x;
            a1 += kv.x * ux.y + kv.y * uy.y + kv.z * uz.y + kv.w * uw.y;
            a2 += kv.x * ux.z + kv.y * uy.z + kv.z * uz.z + kv.w * uw.z;
            a3 += kv.x * ux.w + kv.y * uy.w + kv.z * uz.w + kv.w * uw.w;
        }
        // key padding mask + diagonal blinding (query position is 0 -> mask k==0)
        bool masked = (kmv != 1) || ((k0 + t) == 0);
        s0 = masked ? NEGF : a0;
        s1 = masked ? NEGF : a1;
        s2 = masked ? NEGF : a2;
        s3 = masked ? NEGF : a3;
    }

    // ---- warp+block max per head ----
    float m0 = s0, m1 = s1, m2 = s2, m3 = s3;
    #pragma unroll
    for (int o = 16; o; o >>= 1) {
        m0 = fmaxf(m0, __shfl_xor_sync(0xffffffffu, m0, o));
        m1 = fmaxf(m1, __shfl_xor_sync(0xffffffffu, m1, o));
        m2 = fmaxf(m2, __shfl_xor_sync(0xffffffffu, m2, o));
        m3 = fmaxf(m3, __shfl_xor_sync(0xffffffffu, m3, o));
    }
    if (lane == 0) {
        wred[wid * 4 + 0] = m0; wred[wid * 4 + 1] = m1;
        wred[wid * 4 + 2] = m2; wred[wid * 4 + 3] = m3;
    }
    __syncthreads();
    if (t < 4) {
        float m = wred[t];
        #pragma unroll
        for (int w = 1; w < 8; w++) m = fmaxf(m, wred[w * 4 + t]);
        mh[t] = m;
    }
    __syncthreads();

    // ---- p = exp(s - m), store packed; block sum per head ----
    float p0 = __expf(s0 - mh[0]);
    float p1 = __expf(s1 - mh[1]);
    float p2 = __expf(s2 - mh[2]);
    float p3 = __expf(s3 - mh[3]);
    p4[t] = make_float4(p0, p1, p2, p3);
    float l0 = p0, l1 = p1, l2 = p2, l3 = p3;
    #pragma unroll
    for (int o = 16; o; o >>= 1) {
        l0 += __shfl_xor_sync(0xffffffffu, l0, o);
        l1 += __shfl_xor_sync(0xffffffffu, l1, o);
        l2 += __shfl_xor_sync(0xffffffffu, l2, o);
        l3 += __shfl_xor_sync(0xffffffffu, l3, o);
    }
    if (lane == 0) {
        wred[wid * 4 + 0] = l0; wred[wid * 4 + 1] = l1;
        wred[wid * 4 + 2] = l2; wred[wid * 4 + 3] = l3;
    }
    __syncthreads();
    if (t < 4) {
        float l = wred[t];
        #pragma unroll
        for (int w = 1; w < 8; w++) l += wred[w * 4 + t];
        g_pm[(b * SPLIT + split) * HH + t] = mh[t];
        g_pl[(b * SPLIT + split) * HH + t] = l;
    }

    // ---- phase 2: weighted key sum. thread = (d, k-quarter); acc over 4 heads ----
    {
        int d = t & 63, q = t >> 6;
        float ax = 0.f, ay = 0.f, az = 0.f, aw = 0.f;
        const int kb = q * 64;
        #pragma unroll 4
        for (int kk = 0; kk < 64; kk++) {
            float kv = ks[(kb + kk) * STRIDE + d];
            float4 p = p4[kb + kk];
            ax += p.x * kv; ay += p.y * kv; az += p.z * kv; aw += p.w * kv;
        }
        accm[t] = make_float4(ax, ay, az, aw);
    }
    __syncthreads();
    if (t < 64) {
        float4 a = accm[t], c = accm[64 + t], d4 = accm[128 + t], e = accm[192 + t];
        float4 r;
        r.x = a.x + c.x + d4.x + e.x;
        r.y = a.y + c.y + d4.y + e.y;
        r.z = a.z + c.z + d4.z + e.z;
        r.w = a.w + c.w + d4.w + e.w;
        g_pacc[(b * SPLIT + split) * DD + t] = r;
    }
}

// Kernel B: all global loads issued up-front into smem (max MLP), then a pure
// smem compute chain.
__global__ __launch_bounds__(256) void combine_ffn_kernel(
    const float* __restrict__ queries, const int* __restrict__ query_mask,
    const float* __restrict__ W_V,
    const float* __restrict__ fw1, const float* __restrict__ fw2,
    const float* __restrict__ fb1, const float* __restrict__ fb2,
    float* __restrict__ out)
{
    extern __shared__ float sm[];
    const int b = blockIdx.x;
    const int t = threadIdx.x;

    float* fw1_s = sm + BF_FW1;
    float* fw2_s = sm + BF_FW2;
    float* wv_s  = sm + BF_WV;
    float4* pacc_s = (float4*)(sm + BF_PACC);
    float* fb1_s = sm + BF_FB1;
    float* hid_s = sm + BF_HID;
    float* part_s = sm + BF_PART;
    float* s_sm  = sm + BF_SSM;
    float* q_s   = sm + BF_QS;
    float* fb2_s = sm + BF_FB2;
    float* res_s = sm + BF_RES;
    float* m_s   = sm + BF_MS;
    float* l_s   = sm + BF_LS;
    float* f_s   = sm + BF_FS;
    float* sc_s  = sm + BF_SC;

    // ================= prefetch: issue EVERYTHING before first sync =========
    {
        const float4* g1 = (const float4*)fw1;         // 4096 float4
        const float4* g2 = (const float4*)fw2;         // 4096 float4
        const float4* gv = (const float4*)W_V;         // 1024 float4
        float4* s1 = (float4*)fw1_s;
        float4* s2 = (float4*)fw2_s;
        float4* sv = (float4*)wv_s;

        // scratch for this batch (small, needed first by compute chain)
        pacc_s[t] = g_pacc[b * (SPLIT * DD) + t];
        if (t < 16) {
            m_s[t] = g_pm[b * 16 + t];
            l_s[t] = g_pl[b * 16 + t];
        } else if (t < 32) {
            ((float4*)q_s)[t - 16] = ((const float4*)(queries + (size_t)b * TT * DD))[t - 16];
        } else if (t < 48) {
            ((float4*)fb2_s)[t - 32] = ((const float4*)fb2)[t - 32];
        } else if (t < 112) {
            ((float4*)fb1_s)[t - 48] = ((const float4*)fb1)[t - 48];
        }
        #pragma unroll
        for (int i = 0; i < 16; i++) s1[t + i * 256] = g1[t + i * 256];
        #pragma unroll
        for (int i = 0; i < 16; i++) s2[t + i * 256] = g2[t + i * 256];
        #pragma unroll
        for (int i = 0; i < 4; i++)  sv[t + i * 256] = gv[t + i * 256];
    }
    __syncthreads();

    // ================= compute chain (smem only) ============================
    if (t < HH) {
        float M = m_s[t];
        #pragma unroll
        for (int s = 1; s < SPLIT; s++) M = fmaxf(M, m_s[s * HH + t]);
        float L = 0.f;
        #pragma unroll
        for (int s = 0; s < SPLIT; s++) {
            float f = __expf(m_s[s * HH + t] - M);
            f_s[s * HH + t] = f;
            L += l_s[s * HH + t] * f;
        }
        float qm = (float)query_mask[b * TT];   // query position 0 mask
        sc_s[t] = qm / L;
    }
    __syncthreads();

    // s[h][d] = (sum over splits of acc * factor) * qm / L
    {
        int d = t & 63, h = t >> 6;
        const float* pa = (const float*)pacc_s;
        float S = 0.f;
        #pragma unroll
        for (int s = 0; s < SPLIT; s++)
            S += pa[(s * DD + d) * 4 + h] * f_s[s * HH + h];
        s_sm[h * DD + d] = S * sc_s[h];
    }
    __syncthreads();

    // out[j] = sum_d s[h(j)][d] * W_V[d][j]; residual with queries[b,0,:]
    {
        int j = t & 63, q = t >> 6;
        int h = j >> 4;
        float a = 0.f;
        #pragma unroll
        for (int d = q * 16; d < q * 16 + 16; d++) a += s_sm[h * DD + d] * wv_s[d * 64 + j];
        part_s[t] = a;
    }
    __syncthreads();
    if (t < 64) {
        float o = part_s[t] + part_s[64 + t] + part_s[128 + t] + part_s[192 + t];
        res_s[t] = o + q_s[t];
    }
    __syncthreads();

    // hidden = leaky_relu(res @ fw1 + fb1), 256 units
    {
        float a = fb1_s[t];
        #pragma unroll
        for (int j = 0; j < 64; j++) a += res_s[j] * fw1_s[j * 256 + t];
        hid_s[t] = (a > 0.f) ? a : 0.2f * a;
    }
    __syncthreads();

    // final = res + hidden @ fw2 + fb2
    {
        int j = t & 63, q = t >> 6;
        float a = 0.f;
        #pragma unroll
        for (int m = q * 64; m < q * 64 + 64; m++) a += hid_s[m] * fw2_s[m * 64 + j];
        part_s[t] = a;
    }
    __syncthreads();
    if (t < 64) {
        out[b * 64 + t] = res_s[t] + fb2_s[t]
                        + part_s[t] + part_s[64 + t] + part_s[128 + t] + part_s[192 + t];
    }
}

extern "C" void kernel_launch(void* const* d_in, const int* in_sizes, int n_in,
                              void* d_out, int out_size)
{
    const float* queries = (const float*)d_in[0];
    const float* keys    = (const float*)d_in[1];
    const int*   qmask   = (const int*)d_in[2];
    const int*   kmask   = (const int*)d_in[3];
    const float* W_Q     = (const float*)d_in[4];
    const float* W_K     = (const float*)d_in[5];
    const float* W_V     = (const float*)d_in[6];
    const float* fw1     = (const float*)d_in[7];
    const float* fw2     = (const float*)d_in[8];
    const float* fb1     = (const float*)d_in[9];
    const float* fb2     = (const float*)d_in[10];
    float* out = (float*)d_out;

    cudaFuncSetAttribute(attn_partial_kernel,
                         cudaFuncAttributeMaxDynamicSharedMemorySize, SMEM_BYTES);
    cudaFuncSetAttribute(combine_ffn_kernel,
                         cudaFuncAttributeMaxDynamicSharedMemorySize, BSM_BYTES);

    attn_partial_kernel<<<dim3(SPLIT, BB), 256, SMEM_BYTES>>>(queries, keys, kmask, W_Q, W_K);
    combine_ffn_kernel<<<BB, 256, BSM_BYTES>>>(queries, qmask, W_V, fw1, fw2, fb1, fb2, out);
}

// round 4
// speedup vs baseline: 1.1267x; 1.0292x over previous
#include <cuda_runtime.h>
#include <cuda_bf16.h>

// Problem constants
#define BB 64
#define TT 1024
#define DD 64
#define HH 4
#define SPLIT 4
#define RPC 256        // key rows per CTA in kernel A
#define STRIDE 68      // smem row stride in floats
#define NEGF (-4294967296.0f)   // float32(-2^32+1)

// ---------------- kernel A smem layout (floats) ----------------
#define OFF_KS   0
#define OFF_P4   17408            // 256*68
#define OFF_ACC  18432            // +1024
#define OFF_U    19456            // +1024
#define OFF_Q0   19712            // +256
#define OFF_QH   19776            // +64
#define OFF_WRED 19840            // +64
#define OFF_MH   19872            // +32
#define SMEM_FLOATS 19876
#define SMEM_BYTES (SMEM_FLOATS * 4)

// ---------------- kernel B smem layout (floats) ----------------
#define BF_WV    0                // 4096  (W_V full, 64x64)
#define BF_FW1   4096             // 4096  (fw1 column slice [64][64])
#define BF_FW2   8192             // 4096  (fw2 row slice [64][64])
#define BF_PACC  12288            // 1024  (256 float4)
#define BF_SSM   13312            // 256
#define BF_PART  13568            // 256
#define BF_QS    13824            // 64
#define BF_FB1   13888            // 64   (slice)
#define BF_FB2   13952            // 64
#define BF_RES   14016            // 64
#define BF_HID   14080            // 64
#define BF_MS    14144            // 16
#define BF_LS    14160            // 16
#define BF_FS    14176            // 16
#define BF_SC    14192            // 4
#define BF_QM    14196            // 1
#define BSM_FLOATS 14200
#define BSM_BYTES (BSM_FLOATS * 4)

// Cross-kernel scratch (no cudaMalloc allowed)
__device__ float4 g_pacc[BB * SPLIT * DD];   // [b][split][d] -> 4 heads packed
__device__ float  g_pm[BB * SPLIT * HH];     // running max per (b,split,h)
__device__ float  g_pl[BB * SPLIT * HH];     // exp-sum per (b,split,h)

__global__ __launch_bounds__(256) void attn_partial_kernel(
    const float* __restrict__ queries, const float* __restrict__ keys,
    const int* __restrict__ key_mask,
    const float* __restrict__ W_Q, const float* __restrict__ W_K,
    float* __restrict__ out)
{
    extern __shared__ float sm[];
    float*  ks   = sm + OFF_KS;
    float4* p4   = (float4*)(sm + OFF_P4);
    float4* accm = (float4*)(sm + OFF_ACC);
    float*  u    = sm + OFF_U;
    float*  q0   = sm + OFF_Q0;
    float*  Qh   = sm + OFF_QH;
    float*  wred = sm + OFF_WRED;
    float*  mh   = sm + OFF_MH;

    const int split = blockIdx.x;
    const int b     = blockIdx.y;
    const int t     = threadIdx.x;
    const int k0    = split * RPC;
    const int lane  = t & 31;
    const int wid   = t >> 5;

    // zero the output so kernel B can accumulate with atomics
    if (split == 0 && t < 64) out[b * 64 + t] = 0.f;

    // ---- load key tile [RPC x 64] into smem (coalesced float4) ----
    const float4* kg = (const float4*)(keys + ((size_t)b * TT + k0) * DD);
    #pragma unroll
    for (int i = 0; i < 16; i++) {
        int idx = t + i * 256;
        int row = idx >> 4, c = idx & 15;
        float4 v = kg[idx];
        *(float4*)&ks[row * STRIDE + c * 4] = v;
    }
    const int kmv = key_mask[b * TT + k0 + t];

    if (t < 64) q0[t] = queries[(size_t)b * TT * DD + t];
    __syncthreads();

    // ---- Qh[j] = sum_i q0[i] * W_Q[i][j] ----
    {
        int j = t & 63, q = t >> 6;
        float a = 0.f;
        #pragma unroll
        for (int i = q * 16; i < q * 16 + 16; i++) a += q0[i] * W_Q[i * 64 + j];
        ((float*)accm)[t] = a;
    }
    __syncthreads();
    if (t < 64) {
        float* pr = (float*)accm;
        Qh[t] = pr[t] + pr[64 + t] + pr[128 + t] + pr[192 + t];
    }
    __syncthreads();

    // ---- u[h][d] = 0.25 * sum_j W_K[d][h*16+j] * Qh[h*16+j], stored u[d*4+h] ----
    {
        int d = t & 63, h = t >> 6;
        const float4* wr  = (const float4*)(W_K + d * 64 + h * 16);
        const float4* qh4 = (const float4*)(Qh + h * 16);
        float a = 0.f;
        #pragma unroll
        for (int c = 0; c < 4; c++) {
            float4 w = wr[c]; float4 q = qh4[c];
            a += w.x * q.x + w.y * q.y + w.z * q.z + w.w * q.w;
        }
        u[d * 4 + h] = a * 0.25f;
    }
    __syncthreads();

    // ---- phase 1: thread t = key row t; scores for 4 heads ----
    float s0, s1, s2, s3;
    {
        const float4* krow = (const float4*)&ks[t * STRIDE];
        const float4* u4 = (const float4*)u;
        float a0 = 0.f, a1 = 0.f, a2 = 0.f, a3 = 0.f;
        #pragma unroll
        for (int c = 0; c < 16; c++) {
            float4 kv = krow[c];
            float4 ux = u4[4 * c + 0], uy = u4[4 * c + 1];
            float4 uz = u4[4 * c + 2], uw = u4[4 * c + 3];
            a0 += kv.x * ux.x + kv.y * uy.x + kv.z * uz.x + kv.w * uw.x;
            a1 += kv.x * ux.y + kv.y * uy.y + kv.z * uz.y + kv.w * uw.y;
            a2 += kv.x * ux.z + kv.y * uy.z + kv.z * uz.z + kv.w * uw.z;
            a3 += kv.x * ux.w + kv.y * uy.w + kv.z * uz.w + kv.w * uw.w;
        }
        bool masked = (kmv != 1) || ((k0 + t) == 0);
        s0 = masked ? NEGF : a0;
        s1 = masked ? NEGF : a1;
        s2 = masked ? NEGF : a2;
        s3 = masked ? NEGF : a3;
    }

    // ---- warp+block max per head ----
    float m0 = s0, m1 = s1, m2 = s2, m3 = s3;
    #pragma unroll
    for (int o = 16; o; o >>= 1) {
        m0 = fmaxf(m0, __shfl_xor_sync(0xffffffffu, m0, o));
        m1 = fmaxf(m1, __shfl_xor_sync(0xffffffffu, m1, o));
        m2 = fmaxf(m2, __shfl_xor_sync(0xffffffffu, m2, o));
        m3 = fmaxf(m3, __shfl_xor_sync(0xffffffffu, m3, o));
    }
    if (lane == 0) {
        wred[wid * 4 + 0] = m0; wred[wid * 4 + 1] = m1;
        wred[wid * 4 + 2] = m2; wred[wid * 4 + 3] = m3;
    }
    __syncthreads();
    if (t < 4) {
        float m = wred[t];
        #pragma unroll
        for (int w = 1; w < 8; w++) m = fmaxf(m, wred[w * 4 + t]);
        mh[t] = m;
    }
    __syncthreads();

    // ---- p = exp(s - m); block sum per head ----
    float p0 = __expf(s0 - mh[0]);
    float p1 = __expf(s1 - mh[1]);
    float p2 = __expf(s2 - mh[2]);
    float p3 = __expf(s3 - mh[3]);
    p4[t] = make_float4(p0, p1, p2, p3);
    float l0 = p0, l1 = p1, l2 = p2, l3 = p3;
    #pragma unroll
    for (int o = 16; o; o >>= 1) {
        l0 += __shfl_xor_sync(0xffffffffu, l0, o);
        l1 += __shfl_xor_sync(0xffffffffu, l1, o);
        l2 += __shfl_xor_sync(0xffffffffu, l2, o);
        l3 += __shfl_xor_sync(0xffffffffu, l3, o);
    }
    if (lane == 0) {
        wred[wid * 4 + 0] = l0; wred[wid * 4 + 1] = l1;
        wred[wid * 4 + 2] = l2; wred[wid * 4 + 3] = l3;
    }
    __syncthreads();
    if (t < 4) {
        float l = wred[t];
        #pragma unroll
        for (int w = 1; w < 8; w++) l += wred[w * 4 + t];
        g_pm[(b * SPLIT + split) * HH + t] = mh[t];
        g_pl[(b * SPLIT + split) * HH + t] = l;
    }

    // ---- phase 2: weighted key sum ----
    {
        int d = t & 63, q = t >> 6;
        float ax = 0.f, ay = 0.f, az = 0.f, aw = 0.f;
        const int kb = q * 64;
        #pragma unroll 4
        for (int kk = 0; kk < 64; kk++) {
            float kv = ks[(kb + kk) * STRIDE + d];
            float4 p = p4[kb + kk];
            ax += p.x * kv; ay += p.y * kv; az += p.z * kv; aw += p.w * kv;
        }
        accm[t] = make_float4(ax, ay, az, aw);
    }
    __syncthreads();
    if (t < 64) {
        float4 a = accm[t], c = accm[64 + t], d4 = accm[128 + t], e = accm[192 + t];
        float4 r;
        r.x = a.x + c.x + d4.x + e.x;
        r.y = a.y + c.y + d4.y + e.y;
        r.z = a.z + c.z + d4.z + e.z;
        r.w = a.w + c.w + d4.w + e.w;
        g_pacc[(b * SPLIT + split) * DD + t] = r;
    }
}

// Kernel B: 4 CTAs per batch. CTA q owns hidden slice [64q, 64q+64) and the
// matching fw1 column-slice / fw2 row-slice (16 KB each). All loads fit one
// L2 wave. Partial outputs accumulate into out[] via atomicAdd (out zeroed
// by kernel A).
__global__ __launch_bounds__(256) void combine_ffn_kernel(
    const float* __restrict__ queries, const int* __restrict__ query_mask,
    const float* __restrict__ W_V,
    const float* __restrict__ fw1, const float* __restrict__ fw2,
    const float* __restrict__ fb1, const float* __restrict__ fb2,
    float* __restrict__ out)
{
    extern __shared__ float sm[];
    const int q = blockIdx.x;   // hidden-slice index 0..3
    const int b = blockIdx.y;
    const int t = threadIdx.x;

    float*  wv_s   = sm + BF_WV;
    float*  fw1_s  = sm + BF_FW1;
    float*  fw2_s  = sm + BF_FW2;
    float4* pacc_s = (float4*)(sm + BF_PACC);
    float*  s_sm   = sm + BF_SSM;
    float*  part_s = sm + BF_PART;
    float*  q_s    = sm + BF_QS;
    float*  fb1_s  = sm + BF_FB1;
    float*  fb2_s  = sm + BF_FB2;
    float*  res_s  = sm + BF_RES;
    float*  hid_s  = sm + BF_HID;
    float*  m_s    = sm + BF_MS;
    float*  l_s    = sm + BF_LS;
    float*  f_s    = sm + BF_FS;
    float*  sc_s   = sm + BF_SC;
    float*  qm_s   = sm + BF_QM;

    // ---- prefetch everything (one L2 wave: ~13 float4 per thread) ----
    {
        const float4* gv = (const float4*)W_V;
        // fw2 row slice: rows [64q, 64q+64), row stride 64 floats -> offset q*64*64
        const float4* g2 = (const float4*)(fw2 + q * 64 * 64);
        float4* sv = (float4*)wv_s;
        float4* s1 = (float4*)fw1_s;
        float4* s2 = (float4*)fw2_s;

        pacc_s[t] = g_pacc[b * (SPLIT * DD) + t];
        if (t < 16) {
            m_s[t] = g_pm[b * 16 + t];
            l_s[t] = g_pl[b * 16 + t];
        } else if (t < 32) {
            ((float4*)q_s)[t - 16] = ((const float4*)(queries + (size_t)b * TT * DD))[t - 16];
        } else if (t < 48) {
            ((float4*)fb2_s)[t - 32] = ((const float4*)fb2)[t - 32];
        } else if (t < 64) {
            ((float4*)fb1_s)[t - 48] = ((const float4*)(fb1 + q * 64))[t - 48];
        } else if (t == 64) {
            qm_s[0] = (float)query_mask[b * TT];
        }
        #pragma unroll
        for (int i = 0; i < 4; i++) sv[t + i * 256] = gv[t + i * 256];
        // fw1 column slice: fw1[j][64q + m]; fw1 row stride = 256 floats = 64 f4
        #pragma unroll
        for (int i = 0; i < 4; i++) {
            int idx = t + i * 256;
            int row = idx >> 4, c = idx & 15;
            s1[idx] = ((const float4*)fw1)[row * 64 + q * 16 + c];
        }
        #pragma unroll
        for (int i = 0; i < 4; i++) s2[t + i * 256] = g2[t + i * 256];
    }
    __syncthreads();

    // ---- softmax split combine ----
    if (t < HH) {
        float M = m_s[t];
        #pragma unroll
        for (int s = 1; s < SPLIT; s++) M = fmaxf(M, m_s[s * HH + t]);
        float L = 0.f;
        #pragma unroll
        for (int s = 0; s < SPLIT; s++) {
            float f = __expf(m_s[s * HH + t] - M);
            f_s[s * HH + t] = f;
            L += l_s[s * HH + t] * f;
        }
        sc_s[t] = qm_s[0] / L;
    }
    __syncthreads();

    // s[h][d] = (sum over splits of acc * factor) * qm / L
    {
        int d = t & 63, h = t >> 6;
        const float* pa = (const float*)pacc_s;
        float S = 0.f;
        #pragma unroll
        for (int s = 0; s < SPLIT; s++)
            S += pa[(s * DD + d) * 4 + h] * f_s[s * HH + h];
        s_sm[h * DD + d] = S * sc_s[h];
    }
    __syncthreads();

    // res[j] = (s[h(j)] @ W_V[:,j]) + queries[b,0,j]
    {
        int j = t & 63, qq = t >> 6;
        int h = j >> 4;
        float a = 0.f;
        #pragma unroll
        for (int d = qq * 16; d < qq * 16 + 16; d++) a += s_sm[h * DD + d] * wv_s[d * 64 + j];
        part_s[t] = a;
    }
    __syncthreads();
    if (t < 64) {
        float o = part_s[t] + part_s[64 + t] + part_s[128 + t] + part_s[192 + t];
        res_s[t] = o + q_s[t];
    }
    __syncthreads();

    // hidden slice: hid[m] = leaky_relu(res @ fw1_slice[:,m] + fb1[64q+m])
    {
        int m = t & 63, jq = t >> 6;
        float a = 0.f;
        #pragma unroll
        for (int j = jq * 16; j < jq * 16 + 16; j++) a += res_s[j] * fw1_s[j * 64 + m];
        part_s[t] = a;
    }
    __syncthreads();
    if (t < 64) {
        float a = part_s[t] + part_s[64 + t] + part_s[128 + t] + part_s[192 + t] + fb1_s[t];
        hid_s[t] = (a > 0.f) ? a : 0.2f * a;
    }
    __syncthreads();

    // output partial: sum over this CTA's 64 hidden units
    {
        int j = t & 63, mq = t >> 6;
        float a = 0.f;
        #pragma unroll
        for (int m2 = mq * 16; m2 < mq * 16 + 16; m2++) a += hid_s[m2] * fw2_s[m2 * 64 + j];
        part_s[t] = a;
    }
    __syncthreads();
    if (t < 64) {
        float v = part_s[t] + part_s[64 + t] + part_s[128 + t] + part_s[192 + t];
        if (q == 0) v += res_s[t] + fb2_s[t];
        atomicAdd(&out[b * 64 + t], v);
    }
}

extern "C" void kernel_launch(void* const* d_in, const int* in_sizes, int n_in,
                              void* d_out, int out_size)
{
    const float* queries = (const float*)d_in[0];
    const float* keys    = (const float*)d_in[1];
    const int*   qmask   = (const int*)d_in[2];
    const int*   kmask   = (const int*)d_in[3];
    const float* W_Q     = (const float*)d_in[4];
    const float* W_K     = (const float*)d_in[5];
    const float* W_V     = (const float*)d_in[6];
    const float* fw1     = (const float*)d_in[7];
    const float* fw2     = (const float*)d_in[8];
    const float* fb1     = (const float*)d_in[9];
    const float* fb2     = (const float*)d_in[10];
    float* out = (float*)d_out;

    cudaFuncSetAttribute(attn_partial_kernel,
                         cudaFuncAttributeMaxDynamicSharedMemorySize, SMEM_BYTES);
    cudaFuncSetAttribute(combine_ffn_kernel,
                         cudaFuncAttributeMaxDynamicSharedMemorySize, BSM_BYTES);

    attn_partial_kernel<<<dim3(SPLIT, BB), 256, SMEM_BYTES>>>(queries, keys, kmask, W_Q, W_K, out);
    combine_ffn_kernel<<<dim3(SPLIT, BB), 256, BSM_BYTES>>>(queries, qmask, W_V, fw1, fw2, fb1, fb2, out);
}